// round 1
// baseline (speedup 1.0000x reference)
#include <cuda_runtime.h>

// Shapes (fixed for this problem)
#define BB 32
#define SS 128
#define EE 512
#define FF 2048

#define ECH 256   // e-chunk staged in shared for GEMM1
#define FCH 256   // f-chunk staged in shared for GEMM2

typedef unsigned long long u64;

// 33.5 MB scratch for h = x@W1 + b1, layout [s][b][f]
__device__ float g_h[(size_t)SS * BB * FF];

__device__ __forceinline__ u64 pack2(float lo, float hi) {
    u64 r; asm("mov.b64 %0, {%1, %2};" : "=l"(r) : "f"(lo), "f"(hi)); return r;
}
__device__ __forceinline__ void unpack2(u64 v, float& lo, float& hi) {
    asm("mov.b64 {%0, %1}, %2;" : "=f"(lo), "=f"(hi) : "l"(v));
}
// packed dual fp32 FMA (SASS FFMA2) — acc += a * b elementwise on f32x2
__device__ __forceinline__ void ffma2(u64& acc, u64 a, u64 b) {
    asm("fma.rn.f32x2 %0, %1, %2, %0;" : "+l"(acc) : "l"(a), "l"(b));
}

// ---------------------------------------------------------------------------
// GEMM1: h[s][b][f] = sum_e x[b][s][e] * W1[s][e][f] + b1[s][f]
// grid (4, 128): blockIdx.y = s, blockIdx.x = f-tile of 512
// 256 threads, each owns f0 = tile*512 + tid*2 and f1 = f0+1, all 32 b rows.
// ---------------------------------------------------------------------------
__global__ __launch_bounds__(256) void k_gemm1(const float* __restrict__ x,
                                               const float* __restrict__ W1,
                                               const float* __restrict__ b1) {
    // x chunk staged as b-pairs: xs2[e_local][bp], row padded to 17 u64 (conflict-free fill)
    __shared__ u64 xs2[ECH * 17];
    float* xsf = reinterpret_cast<float*>(xs2);

    const int s   = blockIdx.y;
    const int tid = threadIdx.x;
    const int f0  = blockIdx.x * 512 + tid * 2;

    u64 acc0[16], acc1[16];
#pragma unroll
    for (int i = 0; i < 16; i++) { acc0[i] = 0ull; acc1[i] = 0ull; }

    for (int ec = 0; ec < EE; ec += ECH) {
        __syncthreads();
        // cooperative fill: coalesced global read over e, scatter to b-pair layout
        for (int idx = tid; idx < BB * ECH; idx += 256) {
            int b  = idx >> 8;           // /ECH
            int el = idx & (ECH - 1);
            float v = x[((size_t)b * SS + s) * EE + ec + el];
            xsf[el * 34 + (b >> 1) * 2 + (b & 1)] = v;
        }
        __syncthreads();

        const float* wp = W1 + ((size_t)s * EE + ec) * FF + f0;
#pragma unroll 4
        for (int el = 0; el < ECH; el++) {
            float2 w = *reinterpret_cast<const float2*>(wp);
            wp += FF;
            u64 wlo = pack2(w.x, w.x);
            u64 whi = pack2(w.y, w.y);
            const u64* xr = xs2 + el * 17;
#pragma unroll
            for (int bp = 0; bp < 16; bp++) {
                u64 xv = xr[bp];          // LDS.64 broadcast (same addr across warp)
                ffma2(acc0[bp], xv, wlo);
                ffma2(acc1[bp], xv, whi);
            }
        }
    }

    float2 bias = *reinterpret_cast<const float2*>(b1 + (size_t)s * FF + f0);
#pragma unroll
    for (int bp = 0; bp < 16; bp++) {
        float a00, a10, a01, a11;
        unpack2(acc0[bp], a00, a10);   // (b0,f0), (b1,f0)
        unpack2(acc1[bp], a01, a11);   // (b0,f1), (b1,f1)
        int b0 = bp * 2;
        float2 r0 = make_float2(a00 + bias.x, a01 + bias.y);
        float2 r1 = make_float2(a10 + bias.x, a11 + bias.y);
        *reinterpret_cast<float2*>(&g_h[((size_t)s * BB + b0)     * FF + f0]) = r0;
        *reinterpret_cast<float2*>(&g_h[((size_t)s * BB + b0 + 1) * FF + f0]) = r1;
    }
}

// ---------------------------------------------------------------------------
// GEMM2 + bias + residual + LayerNorm:
//   y[b][s][e] = sum_f h[s][b][f]*W2[s][f][e] + b2[s][e] + x[b][s][e]
//   out = (y - mu) * rsqrt(var + 1e-5) * gamma + beta   (stats over e)
// grid 128 (one CTA per s), 512 threads (one e column each), 32 b rows packed
// as 16 f32x2 accumulators.
// Dynamic shared reused: h-chunk pairs during GEMM, then y staging for LN.
// ---------------------------------------------------------------------------
__global__ __launch_bounds__(512) void k_gemm2(const float* __restrict__ x,
                                               const float* __restrict__ W2,
                                               const float* __restrict__ b2,
                                               const float* __restrict__ gamma,
                                               const float* __restrict__ beta,
                                               float* __restrict__ out) {
    extern __shared__ u64 dyn[];             // hs2[FCH][17] u64, later ys[32][513] floats
    __shared__ float s_mu[BB], s_rs[BB];

    const int s   = blockIdx.x;
    const int tid = threadIdx.x;
    const int e0  = tid;

    u64 acc[16];
#pragma unroll
    for (int i = 0; i < 16; i++) acc[i] = 0ull;

    float* hsf = reinterpret_cast<float*>(dyn);
    for (int fc = 0; fc < FF; fc += FCH) {
        __syncthreads();
        for (int idx = tid; idx < BB * FCH; idx += 512) {
            int b  = idx >> 8;            // /FCH
            int fl = idx & (FCH - 1);
            float v = g_h[((size_t)s * BB + b) * FF + fc + fl];
            hsf[fl * 34 + (b >> 1) * 2 + (b & 1)] = v;
        }
        __syncthreads();

        const float* wp = W2 + ((size_t)s * FF + fc) * EE + e0;
#pragma unroll 4
        for (int fl = 0; fl < FCH; fl++) {
            float w = *wp;
            wp += EE;
            u64 wpair = pack2(w, w);
            const u64* hr = dyn + fl * 17;
#pragma unroll
            for (int bp = 0; bp < 16; bp++) {
                ffma2(acc[bp], hr[bp], wpair);
            }
        }
    }
    __syncthreads();   // done with h-chunk region; reuse as ys

    // epilogue: y = acc + b2 + x  -> ys[b][e] (row pad 513)
    float bias = b2[(size_t)s * EE + e0];
    float* ys = reinterpret_cast<float*>(dyn);
#pragma unroll
    for (int bp = 0; bp < 16; bp++) {
        float v0, v1;
        unpack2(acc[bp], v0, v1);
        int b0 = bp * 2;
        float y0 = v0 + bias + x[((size_t)b0 * SS + s) * EE + e0];
        float y1 = v1 + bias + x[((size_t)(b0 + 1) * SS + s) * EE + e0];
        ys[b0 * 513 + e0]       = y0;
        ys[(b0 + 1) * 513 + e0] = y1;
    }
    __syncthreads();

    // LN stats: 16 warps, warp w reduces rows b = w and b = w+16
    const int warp = tid >> 5, lane = tid & 31;
#pragma unroll
    for (int rep = 0; rep < 2; rep++) {
        int b = warp + rep * 16;
        float sum = 0.f, sq = 0.f;
#pragma unroll
        for (int j = 0; j < 16; j++) {
            float v = ys[b * 513 + lane + j * 32];
            sum += v;
            sq  += v * v;
        }
#pragma unroll
        for (int o = 16; o > 0; o >>= 1) {
            sum += __shfl_xor_sync(0xffffffffu, sum, o);
            sq  += __shfl_xor_sync(0xffffffffu, sq,  o);
        }
        if (lane == 0) {
            float mu  = sum * (1.f / EE);
            float var = sq * (1.f / EE) - mu * mu;
            s_mu[b] = mu;
            s_rs[b] = rsqrtf(var + 1e-5f);
        }
    }
    __syncthreads();

    float g  = gamma[e0];
    float be = beta[e0];
#pragma unroll 4
    for (int b = 0; b < BB; b++) {
        float yv = ys[b * 513 + e0];
        out[((size_t)b * SS + s) * EE + e0] = (yv - s_mu[b]) * s_rs[b] * g + be;
    }
}

extern "C" void kernel_launch(void* const* d_in, const int* in_sizes, int n_in,
                              void* d_out, int out_size) {
    const float* x     = (const float*)d_in[0];
    const float* W1    = (const float*)d_in[1];
    const float* b1    = (const float*)d_in[2];
    const float* W2    = (const float*)d_in[3];
    const float* b2    = (const float*)d_in[4];
    const float* gamma = (const float*)d_in[5];
    const float* beta  = (const float*)d_in[6];
    float* out = (float*)d_out;

    // ys region: 32 * 513 * 4 = 65664 B dynamic shared (> 48 KB default)
    cudaFuncSetAttribute(k_gemm2, cudaFuncAttributeMaxDynamicSharedMemorySize, 65664);

    dim3 g1(FF / 512, SS);
    k_gemm1<<<g1, 256>>>(x, W1, b1);
    k_gemm2<<<SS, 512, 65664>>>(x, W2, b2, gamma, beta, out);
}